// round 12
// baseline (speedup 1.0000x reference)
#include <cuda_runtime.h>
#include <cuda_fp16.h>
#include <cstdint>

// Problem constants
#define BATCH   2
#define S_LEN   4096
#define DMODEL  512
#define NHEAD   8
#define DHEAD   64
#define WNBR    32
#define M_TOT   (BATCH * S_LEN)      // 8192

// ---------------------------------------------------------------------------
// PTX helpers — base sm_103 only (NO tcgen05)
// ---------------------------------------------------------------------------
__device__ __forceinline__ uint32_t smem_to_u32(const void* p) {
    uint32_t a;
    asm("{ .reg .u64 t; cvta.to.shared.u64 t, %1; cvt.u32.u64 %0, t; }" : "=r"(a) : "l"(p));
    return a;
}
__device__ __forceinline__ void ldsm_x4(uint32_t* r, uint32_t addr) {
    asm volatile("ldmatrix.sync.aligned.m8n8.x4.shared.b16 {%0,%1,%2,%3}, [%4];"
                 : "=r"(r[0]), "=r"(r[1]), "=r"(r[2]), "=r"(r[3]) : "r"(addr));
}
__device__ __forceinline__ void mma_f16_16816(float* d, const uint32_t* a,
                                              uint32_t b0, uint32_t b1) {
    asm volatile(
        "mma.sync.aligned.m16n8k16.row.col.f32.f16.f16.f32 "
        "{%0,%1,%2,%3}, {%4,%5,%6,%7}, {%8,%9}, {%0,%1,%2,%3};"
        : "+f"(d[0]), "+f"(d[1]), "+f"(d[2]), "+f"(d[3])
        : "r"(a[0]), "r"(a[1]), "r"(a[2]), "r"(a[3]), "r"(b0), "r"(b1));
}
#define CP_ASYNC16(sa, gp) \
    asm volatile("cp.async.cg.shared.global [%0], [%1], 16;" :: "r"(sa), "l"(gp))
#define CP_COMMIT() asm volatile("cp.async.commit_group;")
#define CP_WAIT1()  asm volatile("cp.async.wait_group 1;")
#define CP_WAIT0()  asm volatile("cp.async.wait_group 0;")

// ---------------------------------------------------------------------------
// Scratch (allocation-free rule: device globals)
// ---------------------------------------------------------------------------
__device__ __align__(256) __half g_q16[M_TOT * DMODEL];   // Q fp16
__device__ __align__(256) __half g_k16[M_TOT * DMODEL];   // K fp16
__device__ __align__(256) __half g_v16[M_TOT * DMODEL];   // V fp16
__device__ __align__(256) __half g_x16[M_TOT * DMODEL];   // x fp16 (later attn-out)
// weights fp16: rows 0..511 Wq, 512..1023 Wk, 1024..1535 Wv, 1536..2047 Wo
__device__ __align__(256) __half g_w16[4 * DMODEL * DMODEL];

// ---------------------------------------------------------------------------
// Fused prep: convert x and the 4 weight matrices to fp16
// ---------------------------------------------------------------------------
#define NX4  (M_TOT * DMODEL / 4)            // 1048576
#define NW4  (DMODEL * DMODEL / 4)           // 65536

__global__ __launch_bounds__(256)
void prep_kernel(const float* __restrict__ x,
                 const float* __restrict__ w0, const float* __restrict__ w1,
                 const float* __restrict__ w2, const float* __restrict__ w3,
                 __half* __restrict__ x16, __half* __restrict__ w16)
{
    int i = blockIdx.x * blockDim.x + threadIdx.x;
    const float* src;
    __half* dst;
    int l;
    if (i < NX4) {
        src = x; dst = x16; l = i;
    } else {
        int j = i - NX4;
        int w = j >> 16;  l = j & (NW4 - 1);
        src = (w == 0) ? w0 : (w == 1) ? w1 : (w == 2) ? w2 : w3;
        dst = w16 + (size_t)w * DMODEL * DMODEL;
    }
    float4 v = ((const float4*)src)[l];
    ((__half2*)dst)[l * 2 + 0] = __floats2half2_rn(v.x, v.y);
    ((__half2*)dst)[l * 2 + 1] = __floats2half2_rn(v.z, v.w);
}

// ---------------------------------------------------------------------------
// Pure fp16 HMMA GEMM (round-8 proven config): C = A * B^T, fp32 accum.
// CTA 128x128, BK=32, 256 threads, warp grid 2(M) x 4(N), warp tile 64x32.
// 3-stage cp.async pipeline, one __syncthreads per K-chunk.
// EPI: 0 = fp32 C ; 1 = QKV fp16 (q / k / v selected by n0 block)
// ---------------------------------------------------------------------------
#define ASTRIDE 40
#define TILE_B  (128 * ASTRIDE * 2)   // 10240 B per 128x32 tile
#define BUF_B   (2 * TILE_B)          // A|B = 20480
#define NSTAGE  3
#define GEMM_SMEM (NSTAGE * BUF_B)    // 61440

template <int EPI>
__device__ __forceinline__
void gemm_core(const __half* __restrict__ A, const __half* __restrict__ B,
               float* __restrict__ C, __half* __restrict__ Q16,
               __half* __restrict__ K16, __half* __restrict__ V16)
{
    extern __shared__ char smc[];
    const uint32_t sbase = smem_to_u32(smc);
    const int t = threadIdx.x, lane = t & 31, wid = t >> 5;
    const int wm = wid & 1, wn = wid >> 1;
    const int m0 = blockIdx.y * 128;
    const int n0 = blockIdx.x * 128;

    float acc[4][4][4];
#pragma unroll
    for (int mi = 0; mi < 4; mi++)
#pragma unroll
        for (int ni = 0; ni < 4; ni++)
#pragma unroll
            for (int j = 0; j < 4; j++) acc[mi][ni][j] = 0.0f;

    const int e0row = t >> 2,         e0c = (t & 3) * 8;
    const int e1row = (t + 256) >> 2, e1c = ((t + 256) & 3) * 8;
    const uint32_t so0 = (uint32_t)(e0row * ASTRIDE + e0c) * 2;
    const uint32_t so1 = (uint32_t)(e1row * ASTRIDE + e1c) * 2;

#define LOAD_CHUNK(kc, buf) do { \
    uint32_t bb = sbase + (uint32_t)(buf) * BUF_B; \
    size_t ga0 = (size_t)(m0 + e0row) * DMODEL + (kc) + e0c; \
    size_t ga1 = (size_t)(m0 + e1row) * DMODEL + (kc) + e1c; \
    size_t gb0 = (size_t)(n0 + e0row) * DMODEL + (kc) + e0c; \
    size_t gb1 = (size_t)(n0 + e1row) * DMODEL + (kc) + e1c; \
    CP_ASYNC16(bb + so0,          A + ga0); \
    CP_ASYNC16(bb + so1,          A + ga1); \
    CP_ASYNC16(bb + TILE_B + so0, B + gb0); \
    CP_ASYNC16(bb + TILE_B + so1, B + gb1); \
} while (0)

    // Prologue: 2 chunks in flight
    LOAD_CHUNK(0, 0);
    CP_COMMIT();
    LOAD_CHUNK(32, 1);
    CP_COMMIT();

    const int lrow = lane & 15;
    const int lcol = lane >> 4;

    for (int c = 0; c < 16; c++) {
        CP_WAIT1();                    // chunk c resident
        __syncthreads();               // buf (c+2)%3 free
        if (c < 14) LOAD_CHUNK((c + 2) * 32, (c + 2) % NSTAGE);
        CP_COMMIT();

        const uint32_t ab = sbase + (uint32_t)(c % NSTAGE) * BUF_B;
#pragma unroll
        for (int ks = 0; ks < 2; ks++) {
            uint32_t af[4][4], bf[2][4];
            const int kcol = ks * 2 + lcol;
#pragma unroll
            for (int mi = 0; mi < 4; mi++) {
                uint32_t ad = ab + (uint32_t)(((wm * 64 + mi * 16 + lrow) * ASTRIDE) + kcol * 8) * 2;
                ldsm_x4(af[mi], ad);
            }
#pragma unroll
            for (int nb = 0; nb < 2; nb++) {
                uint32_t bd = ab + TILE_B +
                              (uint32_t)(((wn * 32 + nb * 16 + lrow) * ASTRIDE) + kcol * 8) * 2;
                ldsm_x4(bf[nb], bd);
            }
#pragma unroll
            for (int mi = 0; mi < 4; mi++)
#pragma unroll
                for (int ni = 0; ni < 4; ni++) {
                    const int nb = ni >> 1, nl = ni & 1;
                    mma_f16_16816(acc[mi][ni], af[mi], bf[nb][nl], bf[nb][nl + 2]);
                }
        }
    }
#undef LOAD_CHUNK

    if (EPI == 0) {
#pragma unroll
        for (int mi = 0; mi < 4; mi++) {
            const int r0 = m0 + wm * 64 + mi * 16 + (lane >> 2);
#pragma unroll
            for (int ni = 0; ni < 4; ni++) {
                const int cc = n0 + wn * 32 + ni * 8 + (lane & 3) * 2;
                *(float2*)(C + (size_t)r0 * DMODEL + cc)       = make_float2(acc[mi][ni][0], acc[mi][ni][1]);
                *(float2*)(C + (size_t)(r0 + 8) * DMODEL + cc) = make_float2(acc[mi][ni][2], acc[mi][ni][3]);
            }
        }
    } else {
        __half* dst;
        int nb0;
        if (n0 < 512)       { dst = Q16; nb0 = n0; }
        else if (n0 < 1024) { dst = K16; nb0 = n0 - 512; }
        else                { dst = V16; nb0 = n0 - 1024; }
#pragma unroll
        for (int mi = 0; mi < 4; mi++) {
            const int r0 = m0 + wm * 64 + mi * 16 + (lane >> 2);
#pragma unroll
            for (int ni = 0; ni < 4; ni++) {
                const int cc = nb0 + wn * 32 + ni * 8 + (lane & 3) * 2;
                *(__half2*)(dst + (size_t)r0 * DMODEL + cc) =
                    __floats2half2_rn(acc[mi][ni][0], acc[mi][ni][1]);
                *(__half2*)(dst + (size_t)(r0 + 8) * DMODEL + cc) =
                    __floats2half2_rn(acc[mi][ni][2], acc[mi][ni][3]);
            }
        }
    }
}

__global__ __launch_bounds__(256, 2)
void gemm_qkv(const __half* __restrict__ A, const __half* __restrict__ B,
              __half* __restrict__ Q16, __half* __restrict__ K16, __half* __restrict__ V16)
{
    gemm_core<1>(A, B, nullptr, Q16, K16, V16);
}

__global__ __launch_bounds__(256, 2)
void gemm_out(const __half* __restrict__ A, const __half* __restrict__ B,
              float* __restrict__ C)
{
    gemm_core<0>(A, B, C, nullptr, nullptr, nullptr);
}

// ---------------------------------------------------------------------------
// Pipelined multi-query neighbor attention.
// 444 CTAs (3/SM), each processes queries bs = bid, bid+444, ... (strided:
// all CTAs work the same Hilbert window concurrently -> L2 sharing).
// K tiles double-buffered (2 x 33280 B dynamic smem); K(i+2) staged during
// query i's compute. sj/q metadata double-buffered in static smem; each lane
// caches sj[lane] in a register (shfl-broadcast in V loop) so slots recycle.
// 8 warps = 8 heads. q fp16, V gathered direct from L2. Output fp16.
// ---------------------------------------------------------------------------
#define ATT_CTAS 444
#define KTILE_B  (WNBR * 1040)               // 33280 B
#define ATT_SMEM (2 * KTILE_B)               // 66560 B

__global__ __launch_bounds__(256, 3)
void attn_kernel(const __half* __restrict__ q16,
                 const __half* __restrict__ k16,
                 const __half* __restrict__ v16,
                 const int*   __restrict__ nidx,
                 __half* __restrict__ a16)
{
    extern __shared__ char smc[];
    const uint32_t sbase = smem_to_u32(smc);
    __shared__ int     sj[2][WNBR];
    __shared__ __half2 sqh[2][256];          // 64 half2 per head x 8... [h*32 + j]

    const int bid  = blockIdx.x;
    const int t    = threadIdx.x;
    const int h    = t >> 5;
    const int lane = t & 31;
    const int n    = (M_TOT - 1 - bid) / ATT_CTAS + 1;   // queries for this CTA

    // meta(i) -> slot: neighbor indices + q vector for query i
#define LOADMETA(i, slot) do { \
    if ((i) < n) { \
        int bs_ = bid + (i) * ATT_CTAS; \
        int s_  = bs_ & (S_LEN - 1); \
        if (t < WNBR) sj[slot][t] = nidx[s_ * WNBR + t]; \
        sqh[slot][t] = *(const __half2*)(q16 + (size_t)bs_ * DMODEL + t * 2); \
    } \
} while (0)

    // stage(i) -> K buf slot (always commits, possibly-empty group)
#define STAGEK(i, slot) do { \
    if ((i) < n) { \
        int bs_ = bid + (i) * ATT_CTAS; \
        int b_  = bs_ >> 12; \
        uint32_t kb = sbase + (uint32_t)(slot) * KTILE_B; \
        _Pragma("unroll") \
        for (int ii = 0; ii < 8; ii++) { \
            int e = t + ii * 256; \
            int w = e >> 6, c = e & 63; \
            size_t src = (size_t)(b_ * S_LEN + sj[slot][w]) * DMODEL + c * 8; \
            CP_ASYNC16(kb + (uint32_t)(w * 1040 + c * 16), k16 + src); \
        } \
    } \
    CP_COMMIT(); \
} while (0)

    // Prologue: meta+stage for queries 0 and 1
    LOADMETA(0, 0);
    LOADMETA(1, 1);
    __syncthreads();
    STAGEK(0, 0);
    STAGEK(1, 1);

    for (int i = 0; i < n; i++) {
        const int cur = i & 1;
        const int bs  = bid + i * ATT_CTAS;
        const int b   = bs >> 12;

        CP_WAIT1();                  // K(i) resident (K(i+1) may pend)
        __syncthreads();

        const int sjv = sj[cur][lane];   // lane's neighbor row (reg copy)

        // Scores: lane owns neighbor `lane`; q broadcast from fp16 smem
        float acc = 0.0f;
        {
            const char* kr = smc + cur * KTILE_B + lane * 1040 + h * 128;
            const __half2* qr = &sqh[cur][h * 32];
#pragma unroll
            for (int ii = 0; ii < 8; ii++) {
                uint4 kv = *(const uint4*)(kr + ii * 16);
                uint2 qv = *(const uint2*)(qr + ii * 4);       // 4 half2 = 16B... (2x8B)
                uint2 qv2 = *(const uint2*)(qr + ii * 4 + 2);
                float2 qf0 = __half22float2(*(__half2*)&qv.x);
                float2 qf1 = __half22float2(*(__half2*)&qv.y);
                float2 qf2 = __half22float2(*(__half2*)&qv2.x);
                float2 qf3 = __half22float2(*(__half2*)&qv2.y);
                float2 f0 = __half22float2(*(__half2*)&kv.x);
                float2 f1 = __half22float2(*(__half2*)&kv.y);
                float2 f2 = __half22float2(*(__half2*)&kv.z);
                float2 f3 = __half22float2(*(__half2*)&kv.w);
                acc += qf0.x * f0.x + qf0.y * f0.y + qf1.x * f1.x + qf1.y * f1.y
                     + qf2.x * f2.x + qf2.y * f2.y + qf3.x * f3.x + qf3.y * f3.y;
            }
        }
        float score = acc * 0.125f;

        // Recycle slot `cur` for query i+2: meta, then stage (needs barrier
        // between slot reads above / writes below, and between meta & stage).
        __syncthreads();
        LOADMETA(i + 2, cur);
        __syncthreads();
        STAGEK(i + 2, cur);          // cp.async in flight during softmax/PV

        // Prefetch V rows 0..15 via sjv shuffles (independent of p)
        const __half* vbase = v16 + (size_t)b * S_LEN * DMODEL + h * DHEAD + lane * 2;
        float2 vpre[16];
#pragma unroll
        for (int u = 0; u < 16; u++) {
            int row = __shfl_sync(0xffffffffu, sjv, u);
            vpre[u] = __half22float2(*(const __half2*)(vbase + (size_t)row * DMODEL));
        }

        // Warp softmax
        float m = score;
#pragma unroll
        for (int o = 16; o; o >>= 1) m = fmaxf(m, __shfl_xor_sync(0xffffffffu, m, o));
        float e = __expf(score - m);
        float ssum = e;
#pragma unroll
        for (int o = 16; o; o >>= 1) ssum += __shfl_xor_sync(0xffffffffu, ssum, o);
        float p = e / ssum;

        // PV: prefetched rows, then the remaining two 8-deep batches
        float ox = 0.0f, oy = 0.0f;
#pragma unroll
        for (int u = 0; u < 16; u++) {
            float pw = __shfl_sync(0xffffffffu, p, u);
            ox += pw * vpre[u].x;
            oy += pw * vpre[u].y;
        }
#pragma unroll
        for (int w0 = 16; w0 < WNBR; w0 += 8) {
            float2 vv[8];
#pragma unroll
            for (int u = 0; u < 8; u++) {
                int row = __shfl_sync(0xffffffffu, sjv, w0 + u);
                vv[u] = __half22float2(*(const __half2*)(vbase + (size_t)row * DMODEL));
            }
#pragma unroll
            for (int u = 0; u < 8; u++) {
                float pw = __shfl_sync(0xffffffffu, p, w0 + u);
                ox += pw * vv[u].x;
                oy += pw * vv[u].y;
            }
        }

        // fp16 output (feeds final GEMM directly)
        const size_t oidx = (size_t)bs * DMODEL + h * DHEAD + lane * 2;
        *(__half2*)(a16 + oidx) = __floats2half2_rn(ox, oy);
    }
#undef LOADMETA
#undef STAGEK
}

// ---------------------------------------------------------------------------
extern "C" void kernel_launch(void* const* d_in, const int* in_sizes, int n_in,
                              void* d_out, int out_size)
{
    const float* x    = (const float*)d_in[0];
    const float* Wq   = (const float*)d_in[1];
    const float* Wk   = (const float*)d_in[2];
    const float* Wv   = (const float*)d_in[3];
    const float* Wo   = (const float*)d_in[4];
    const int*   nidx = (const int*)  d_in[5];
    float*       out  = (float*)d_out;

    __half *q16, *k16, *v16, *x16, *w16;
    cudaGetSymbolAddress((void**)&q16, g_q16);
    cudaGetSymbolAddress((void**)&k16, g_k16);
    cudaGetSymbolAddress((void**)&v16, g_v16);
    cudaGetSymbolAddress((void**)&x16, g_x16);
    cudaGetSymbolAddress((void**)&w16, g_w16);

    static int attr_set = 0;
    if (!attr_set) {
        cudaFuncSetAttribute(attn_kernel, cudaFuncAttributeMaxDynamicSharedMemorySize, ATT_SMEM);
        cudaFuncSetAttribute(gemm_qkv,    cudaFuncAttributeMaxDynamicSharedMemorySize, GEMM_SMEM);
        cudaFuncSetAttribute(gemm_out,    cudaFuncAttributeMaxDynamicSharedMemorySize, GEMM_SMEM);
        attr_set = 1;
    }

    const int NW = DMODEL * DMODEL;           // 262144

    prep_kernel<<<(NX4 + 4 * NW4) / 256, 256>>>(x, Wq, Wk, Wv, Wo, x16, w16);

    dim3 qkvgrid(3 * DMODEL / 128, M_TOT / 128);   // (12, 64) = 768 CTAs
    gemm_qkv<<<qkvgrid, 256, GEMM_SMEM>>>(x16, w16, q16, k16, v16);

    attn_kernel<<<ATT_CTAS, 256, ATT_SMEM>>>(q16, k16, v16, nidx, x16);

    dim3 ogrid(DMODEL / 128, M_TOT / 128);         // (4, 64) = 256 CTAs
    gemm_out<<<ogrid, 256, GEMM_SMEM>>>(x16, w16 + 3 * NW, out);
}

// round 13
// speedup vs baseline: 1.1495x; 1.1495x over previous
#include <cuda_runtime.h>
#include <cuda_fp16.h>
#include <cstdint>

// Problem constants
#define BATCH   2
#define S_LEN   4096
#define DMODEL  512
#define NHEAD   8
#define DHEAD   64
#define WNBR    32
#define M_TOT   (BATCH * S_LEN)      // 8192

// ---------------------------------------------------------------------------
// PTX helpers — base sm_103 only (NO tcgen05)
// ---------------------------------------------------------------------------
__device__ __forceinline__ uint32_t smem_to_u32(const void* p) {
    uint32_t a;
    asm("{ .reg .u64 t; cvta.to.shared.u64 t, %1; cvt.u32.u64 %0, t; }" : "=r"(a) : "l"(p));
    return a;
}
__device__ __forceinline__ void ldsm_x4(uint32_t* r, uint32_t addr) {
    asm volatile("ldmatrix.sync.aligned.m8n8.x4.shared.b16 {%0,%1,%2,%3}, [%4];"
                 : "=r"(r[0]), "=r"(r[1]), "=r"(r[2]), "=r"(r[3]) : "r"(addr));
}
__device__ __forceinline__ void mma_f16_16816(float* d, const uint32_t* a,
                                              uint32_t b0, uint32_t b1) {
    asm volatile(
        "mma.sync.aligned.m16n8k16.row.col.f32.f16.f16.f32 "
        "{%0,%1,%2,%3}, {%4,%5,%6,%7}, {%8,%9}, {%0,%1,%2,%3};"
        : "+f"(d[0]), "+f"(d[1]), "+f"(d[2]), "+f"(d[3])
        : "r"(a[0]), "r"(a[1]), "r"(a[2]), "r"(a[3]), "r"(b0), "r"(b1));
}
#define CP_ASYNC16(sa, gp) \
    asm volatile("cp.async.cg.shared.global [%0], [%1], 16;" :: "r"(sa), "l"(gp))
#define CP_COMMIT() asm volatile("cp.async.commit_group;")
#define CP_WAIT1()  asm volatile("cp.async.wait_group 1;")
#define CP_WAIT0()  asm volatile("cp.async.wait_group 0;")

// ---------------------------------------------------------------------------
// Scratch (allocation-free rule: device globals)
// ---------------------------------------------------------------------------
__device__ __align__(256) __half g_q16[M_TOT * DMODEL];   // Q fp16
__device__ __align__(256) __half g_k16[M_TOT * DMODEL];   // K fp16
__device__ __align__(256) __half g_v16[M_TOT * DMODEL];   // V fp16
__device__ __align__(256) __half g_x16[M_TOT * DMODEL];   // x fp16 (later attn-out)
// weights fp16: rows 0..511 Wq, 512..1023 Wk, 1024..1535 Wv, 1536..2047 Wo
__device__ __align__(256) __half g_w16[4 * DMODEL * DMODEL];

// ---------------------------------------------------------------------------
// Fused prep: convert x and the 4 weight matrices to fp16
// ---------------------------------------------------------------------------
#define NX4  (M_TOT * DMODEL / 4)            // 1048576
#define NW4  (DMODEL * DMODEL / 4)           // 65536

__global__ __launch_bounds__(256)
void prep_kernel(const float* __restrict__ x,
                 const float* __restrict__ w0, const float* __restrict__ w1,
                 const float* __restrict__ w2, const float* __restrict__ w3,
                 __half* __restrict__ x16, __half* __restrict__ w16)
{
    int i = blockIdx.x * blockDim.x + threadIdx.x;
    const float* src;
    __half* dst;
    int l;
    if (i < NX4) {
        src = x; dst = x16; l = i;
    } else {
        int j = i - NX4;
        int w = j >> 16;  l = j & (NW4 - 1);
        src = (w == 0) ? w0 : (w == 1) ? w1 : (w == 2) ? w2 : w3;
        dst = w16 + (size_t)w * DMODEL * DMODEL;
    }
    float4 v = ((const float4*)src)[l];
    ((__half2*)dst)[l * 2 + 0] = __floats2half2_rn(v.x, v.y);
    ((__half2*)dst)[l * 2 + 1] = __floats2half2_rn(v.z, v.w);
}

// ---------------------------------------------------------------------------
// Pure fp16 HMMA GEMM (round-8 proven config): C = A * B^T, fp32 accum.
// CTA 128x128, BK=32, 256 threads, warp grid 2(M) x 4(N), warp tile 64x32.
// 3-stage cp.async pipeline, one __syncthreads per K-chunk.
// EPI: 0 = fp32 C ; 1 = QKV fp16 (q / k / v selected by n0 block)
// ---------------------------------------------------------------------------
#define ASTRIDE 40
#define TILE_B  (128 * ASTRIDE * 2)   // 10240 B per 128x32 tile
#define BUF_B   (2 * TILE_B)          // A|B = 20480
#define NSTAGE  3
#define GEMM_SMEM (NSTAGE * BUF_B)    // 61440

template <int EPI>
__device__ __forceinline__
void gemm_core(const __half* __restrict__ A, const __half* __restrict__ B,
               float* __restrict__ C, __half* __restrict__ Q16,
               __half* __restrict__ K16, __half* __restrict__ V16)
{
    extern __shared__ char smc[];
    const uint32_t sbase = smem_to_u32(smc);
    const int t = threadIdx.x, lane = t & 31, wid = t >> 5;
    const int wm = wid & 1, wn = wid >> 1;
    const int m0 = blockIdx.y * 128;
    const int n0 = blockIdx.x * 128;

    float acc[4][4][4];
#pragma unroll
    for (int mi = 0; mi < 4; mi++)
#pragma unroll
        for (int ni = 0; ni < 4; ni++)
#pragma unroll
            for (int j = 0; j < 4; j++) acc[mi][ni][j] = 0.0f;

    const int e0row = t >> 2,         e0c = (t & 3) * 8;
    const int e1row = (t + 256) >> 2, e1c = ((t + 256) & 3) * 8;
    const uint32_t so0 = (uint32_t)(e0row * ASTRIDE + e0c) * 2;
    const uint32_t so1 = (uint32_t)(e1row * ASTRIDE + e1c) * 2;

#define LOAD_CHUNK(kc, buf) do { \
    uint32_t bb = sbase + (uint32_t)(buf) * BUF_B; \
    size_t ga0 = (size_t)(m0 + e0row) * DMODEL + (kc) + e0c; \
    size_t ga1 = (size_t)(m0 + e1row) * DMODEL + (kc) + e1c; \
    size_t gb0 = (size_t)(n0 + e0row) * DMODEL + (kc) + e0c; \
    size_t gb1 = (size_t)(n0 + e1row) * DMODEL + (kc) + e1c; \
    CP_ASYNC16(bb + so0,          A + ga0); \
    CP_ASYNC16(bb + so1,          A + ga1); \
    CP_ASYNC16(bb + TILE_B + so0, B + gb0); \
    CP_ASYNC16(bb + TILE_B + so1, B + gb1); \
} while (0)

    // Prologue: 2 chunks in flight
    LOAD_CHUNK(0, 0);
    CP_COMMIT();
    LOAD_CHUNK(32, 1);
    CP_COMMIT();

    const int lrow = lane & 15;
    const int lcol = lane >> 4;

    for (int c = 0; c < 16; c++) {
        CP_WAIT1();                    // chunk c resident
        __syncthreads();               // buf (c+2)%3 free
        if (c < 14) LOAD_CHUNK((c + 2) * 32, (c + 2) % NSTAGE);
        CP_COMMIT();

        const uint32_t ab = sbase + (uint32_t)(c % NSTAGE) * BUF_B;
#pragma unroll
        for (int ks = 0; ks < 2; ks++) {
            uint32_t af[4][4], bf[2][4];
            const int kcol = ks * 2 + lcol;
#pragma unroll
            for (int mi = 0; mi < 4; mi++) {
                uint32_t ad = ab + (uint32_t)(((wm * 64 + mi * 16 + lrow) * ASTRIDE) + kcol * 8) * 2;
                ldsm_x4(af[mi], ad);
            }
#pragma unroll
            for (int nb = 0; nb < 2; nb++) {
                uint32_t bd = ab + TILE_B +
                              (uint32_t)(((wn * 32 + nb * 16 + lrow) * ASTRIDE) + kcol * 8) * 2;
                ldsm_x4(bf[nb], bd);
            }
#pragma unroll
            for (int mi = 0; mi < 4; mi++)
#pragma unroll
                for (int ni = 0; ni < 4; ni++) {
                    const int nb = ni >> 1, nl = ni & 1;
                    mma_f16_16816(acc[mi][ni], af[mi], bf[nb][nl], bf[nb][nl + 2]);
                }
        }
    }
#undef LOAD_CHUNK

    if (EPI == 0) {
#pragma unroll
        for (int mi = 0; mi < 4; mi++) {
            const int r0 = m0 + wm * 64 + mi * 16 + (lane >> 2);
#pragma unroll
            for (int ni = 0; ni < 4; ni++) {
                const int cc = n0 + wn * 32 + ni * 8 + (lane & 3) * 2;
                *(float2*)(C + (size_t)r0 * DMODEL + cc)       = make_float2(acc[mi][ni][0], acc[mi][ni][1]);
                *(float2*)(C + (size_t)(r0 + 8) * DMODEL + cc) = make_float2(acc[mi][ni][2], acc[mi][ni][3]);
            }
        }
    } else {
        __half* dst;
        int nb0;
        if (n0 < 512)       { dst = Q16; nb0 = n0; }
        else if (n0 < 1024) { dst = K16; nb0 = n0 - 512; }
        else                { dst = V16; nb0 = n0 - 1024; }
#pragma unroll
        for (int mi = 0; mi < 4; mi++) {
            const int r0 = m0 + wm * 64 + mi * 16 + (lane >> 2);
#pragma unroll
            for (int ni = 0; ni < 4; ni++) {
                const int cc = nb0 + wn * 32 + ni * 8 + (lane & 3) * 2;
                *(__half2*)(dst + (size_t)r0 * DMODEL + cc) =
                    __floats2half2_rn(acc[mi][ni][0], acc[mi][ni][1]);
                *(__half2*)(dst + (size_t)(r0 + 8) * DMODEL + cc) =
                    __floats2half2_rn(acc[mi][ni][2], acc[mi][ni][3]);
            }
        }
    }
}

__global__ __launch_bounds__(256, 2)
void gemm_qkv(const __half* __restrict__ A, const __half* __restrict__ B,
              __half* __restrict__ Q16, __half* __restrict__ K16, __half* __restrict__ V16)
{
    gemm_core<1>(A, B, nullptr, Q16, K16, V16);
}

__global__ __launch_bounds__(256, 2)
void gemm_out(const __half* __restrict__ A, const __half* __restrict__ B,
              float* __restrict__ C)
{
    gemm_core<0>(A, B, C, nullptr, nullptr, nullptr);
}

// ---------------------------------------------------------------------------
// Neighbor attention with HMMA scores. One CTA per (b,s); warp = head.
// K staged in smem (pitch 1040B = conflict-free for ldmatrix: 1040=65*16,
// row stride 4 banks -> 8 rows x 16B cover all 32 banks). Scores via
// mma.m16n8k16: A = K rows (2 m-tiles x 4 k-chunks), B = q replicated
// across all 8 N-cols, so each lane ends with S for neighbors
// w = (lane>>2) + 8j, j=0..3 in c0/c2 of the two m-tiles.
// Softmax: 4 local + shfl_xor(4,8,16). PV: scalar direct-L2 gather,
// p broadcast via shfl(p[w>>3], (w&7)*4). Output fp16.
// ---------------------------------------------------------------------------
#define ATT_SMEM (WNBR * 1040)               // 33280 B

__global__ __launch_bounds__(256, 6)
void attn_kernel(const __half* __restrict__ q16,
                 const __half* __restrict__ k16,
                 const __half* __restrict__ v16,
                 const int*   __restrict__ nidx,
                 __half* __restrict__ a16)
{
    extern __shared__ char smc[];
    const uint32_t sbase = smem_to_u32(smc);
    __shared__ int    sj[WNBR];
    __shared__ __half sq16[DMODEL];

    const int bs   = blockIdx.x;
    const int s    = bs & (S_LEN - 1);
    const int b    = bs >> 12;
    const int t    = threadIdx.x;
    const int h    = t >> 5;
    const int lane = t & 31;

    if (t < WNBR) sj[t] = nidx[s * WNBR + t];
    *(__half2*)(sq16 + t * 2) = *(const __half2*)(q16 + (size_t)bs * DMODEL + t * 2);
    __syncthreads();

    // Stage K rows: 32 rows x 1024 B, 64 16B-chunks per row, 8 per thread.
#pragma unroll
    for (int i = 0; i < 8; i++) {
        int e = t + i * 256;
        int w = e >> 6, c = e & 63;
        size_t src = (size_t)(b * S_LEN + sj[w]) * DMODEL + c * 8;
        CP_ASYNC16(sbase + (uint32_t)(w * 1040 + c * 16), k16 + src);
    }
    CP_COMMIT();
    CP_WAIT0();
    __syncthreads();

    // Scores via HMMA. A-frag: lane l -> row (mt*16 + l%16), col-half (l/16)*16B.
    float acc_s[2][4];
#pragma unroll
    for (int mt = 0; mt < 2; mt++)
#pragma unroll
        for (int j = 0; j < 4; j++) acc_s[mt][j] = 0.0f;

#pragma unroll
    for (int kc = 0; kc < 4; kc++) {
        // B frag: B[k][n] = q[h*64 + kc*16 + k] for all n (half2-aligned LDS)
        uint32_t b0 = *(const uint32_t*)(sq16 + h * 64 + kc * 16 + 2 * (lane & 3));
        uint32_t b1 = *(const uint32_t*)(sq16 + h * 64 + kc * 16 + 8 + 2 * (lane & 3));
#pragma unroll
        for (int mt = 0; mt < 2; mt++) {
            uint32_t a[4];
            uint32_t ad = sbase + (uint32_t)((mt * 16 + (lane & 15)) * 1040
                                             + h * 128 + kc * 32 + (lane >> 4) * 16);
            ldsm_x4(a, ad);
            mma_f16_16816(acc_s[mt], a, b0, b1);
        }
    }

    // Lane holds S[w] for w = (lane>>2) + 8j: j=0 -> acc_s[0][0], j=1 -> acc_s[0][2],
    // j=2 -> acc_s[1][0], j=3 -> acc_s[1][2]   (all N-cols identical).
    float sv[4] = { acc_s[0][0] * 0.125f, acc_s[0][2] * 0.125f,
                    acc_s[1][0] * 0.125f, acc_s[1][2] * 0.125f };

    // Softmax across 32 neighbors: local 4, then butterfly over lane bits 2..4.
    float m = fmaxf(fmaxf(sv[0], sv[1]), fmaxf(sv[2], sv[3]));
#pragma unroll
    for (int o = 4; o <= 16; o <<= 1) m = fmaxf(m, __shfl_xor_sync(0xffffffffu, m, o));
    float p[4], ssum = 0.0f;
#pragma unroll
    for (int j = 0; j < 4; j++) { p[j] = __expf(sv[j] - m); ssum += p[j]; }
#pragma unroll
    for (int o = 4; o <= 16; o <<= 1) ssum += __shfl_xor_sync(0xffffffffu, ssum, o);
    const float inv = 1.0f / ssum;
#pragma unroll
    for (int j = 0; j < 4; j++) p[j] *= inv;

    // PV: direct L2 gather, 8-deep batches; p[w] from lane (w&7)*4, reg w>>3.
    float ox = 0.0f, oy = 0.0f;
    const __half* vbase = v16 + (size_t)b * S_LEN * DMODEL + h * DHEAD + lane * 2;
#pragma unroll
    for (int w0 = 0; w0 < WNBR; w0 += 8) {
        float2 vv[8];
#pragma unroll
        for (int u = 0; u < 8; u++)
            vv[u] = __half22float2(*(const __half2*)(vbase + (size_t)sj[w0 + u] * DMODEL));
        const int j = w0 >> 3;
#pragma unroll
        for (int u = 0; u < 8; u++) {
            float pw = __shfl_sync(0xffffffffu, p[j], u * 4);
            ox += pw * vv[u].x;
            oy += pw * vv[u].y;
        }
    }

    // fp16 output (feeds final GEMM directly)
    const size_t oidx = (size_t)bs * DMODEL + h * DHEAD + lane * 2;
    *(__half2*)(a16 + oidx) = __floats2half2_rn(ox, oy);
}

// ---------------------------------------------------------------------------
extern "C" void kernel_launch(void* const* d_in, const int* in_sizes, int n_in,
                              void* d_out, int out_size)
{
    const float* x    = (const float*)d_in[0];
    const float* Wq   = (const float*)d_in[1];
    const float* Wk   = (const float*)d_in[2];
    const float* Wv   = (const float*)d_in[3];
    const float* Wo   = (const float*)d_in[4];
    const int*   nidx = (const int*)  d_in[5];
    float*       out  = (float*)d_out;

    __half *q16, *k16, *v16, *x16, *w16;
    cudaGetSymbolAddress((void**)&q16, g_q16);
    cudaGetSymbolAddress((void**)&k16, g_k16);
    cudaGetSymbolAddress((void**)&v16, g_v16);
    cudaGetSymbolAddress((void**)&x16, g_x16);
    cudaGetSymbolAddress((void**)&w16, g_w16);

    static int attr_set = 0;
    if (!attr_set) {
        cudaFuncSetAttribute(attn_kernel, cudaFuncAttributeMaxDynamicSharedMemorySize, ATT_SMEM);
        cudaFuncSetAttribute(gemm_qkv,    cudaFuncAttributeMaxDynamicSharedMemorySize, GEMM_SMEM);
        cudaFuncSetAttribute(gemm_out,    cudaFuncAttributeMaxDynamicSharedMemorySize, GEMM_SMEM);
        attr_set = 1;
    }

    const int NW = DMODEL * DMODEL;           // 262144

    prep_kernel<<<(NX4 + 4 * NW4) / 256, 256>>>(x, Wq, Wk, Wv, Wo, x16, w16);

    dim3 qkvgrid(3 * DMODEL / 128, M_TOT / 128);   // (12, 64) = 768 CTAs
    gemm_qkv<<<qkvgrid, 256, GEMM_SMEM>>>(x16, w16, q16, k16, v16);

    attn_kernel<<<M_TOT, 256, ATT_SMEM>>>(q16, k16, v16, nidx, x16);

    dim3 ogrid(DMODEL / 128, M_TOT / 128);         // (4, 64) = 256 CTAs
    gemm_out<<<ogrid, 256, GEMM_SMEM>>>(x16, w16 + 3 * NW, out);
}